// round 1
// baseline (speedup 1.0000x reference)
#include <cuda_runtime.h>
#include <math.h>

#define H 128
#define W 128
#define B 8
#define SENTINEL (1 << 28)

// Scratch for per-row 1D squared distances (no device allocation allowed).
__device__ int g_G[H * W];

// Phase 1: one block per row h. Compute union mask over batch, then
// G(h,j) = min over boundary w in this row of (j-w)^2.
__global__ void __launch_bounds__(W) edt_rows(const float* __restrict__ in) {
    const int h = blockIdx.x;
    const int j = threadIdx.x;

    __shared__ int mask[W];

    bool m = false;
#pragma unroll
    for (int b = 0; b < B; b++) {
        m |= in[b * (H * W) + h * W + j] > 0.5f;
    }
    mask[j] = m ? 0 : SENTINEL;  // additive sentinel form for branchless min
    __syncthreads();

    int best = SENTINEL;
#pragma unroll 8
    for (int w = 0; w < W; w++) {
        int d = j - w;
        int v = d * d + mask[w];   // if not boundary, v >= SENTINEL
        best = min(best, v);
    }
    g_G[h * W + j] = best;
}

// Phase 2: one block per output row i. For each column j,
// d2(i,j) = min_h (i-h)^2 + G(h,j); write sqrt broadcast to all batches.
__global__ void __launch_bounds__(W) edt_cols(float* __restrict__ out) {
    const int i = blockIdx.x;
    const int j = threadIdx.x;

    int best = SENTINEL;
#pragma unroll 8
    for (int h = 0; h < H; h++) {
        int d = i - h;
        int v = d * d + g_G[h * W + j];  // coalesced across threads
        best = min(best, v);
    }

    float r = (best >= SENTINEL) ? INFINITY : sqrtf((float)best);

#pragma unroll
    for (int b = 0; b < B; b++) {
        out[b * (H * W) + i * W + j] = r;
    }
}

extern "C" void kernel_launch(void* const* d_in, const int* in_sizes, int n_in,
                              void* d_out, int out_size) {
    const float* in = (const float*)d_in[0];
    float* out = (float*)d_out;

    edt_rows<<<H, W>>>(in);
    edt_cols<<<H, W>>>(out);
}

// round 2
// speedup vs baseline: 1.1284x; 1.1284x over previous
#include <cuda_runtime.h>
#include <math.h>

#define H 128
#define W 128
#define B 8
#define SENTINEL (1 << 28)

// Scratch for per-row 1D squared distances (no device allocation allowed).
__device__ int g_G[H * W];

// Phase 1: one block per row h. Compute union mask over batch, then
// G(h,j) = min over boundary w in this row of (j-w)^2.
__global__ void __launch_bounds__(W) edt_rows(const float* __restrict__ in) {
    const int h = blockIdx.x;
    const int j = threadIdx.x;

    __shared__ int mask[W];

    bool m = false;
#pragma unroll
    for (int b = 0; b < B; b++) {
        m |= in[b * (H * W) + h * W + j] > 0.5f;
    }
    mask[j] = m ? 0 : SENTINEL;  // additive sentinel form for branchless min
    __syncthreads();

    int best = SENTINEL;
#pragma unroll 8
    for (int w = 0; w < W; w++) {
        int d = j - w;
        int v = d * d + mask[w];   // if not boundary, v >= SENTINEL
        best = min(best, v);
    }
    g_G[h * W + j] = best;
}

// Phase 2: one block per output row i. For each column j,
// d2(i,j) = min_h (i-h)^2 + G(h,j); write sqrt broadcast to all batches.
__global__ void __launch_bounds__(W) edt_cols(float* __restrict__ out) {
    const int i = blockIdx.x;
    const int j = threadIdx.x;

    int best = SENTINEL;
#pragma unroll 8
    for (int h = 0; h < H; h++) {
        int d = i - h;
        int v = d * d + g_G[h * W + j];  // coalesced across threads
        best = min(best, v);
    }

    float r = (best >= SENTINEL) ? INFINITY : sqrtf((float)best);

#pragma unroll
    for (int b = 0; b < B; b++) {
        out[b * (H * W) + i * W + j] = r;
    }
}

extern "C" void kernel_launch(void* const* d_in, const int* in_sizes, int n_in,
                              void* d_out, int out_size) {
    const float* in = (const float*)d_in[0];
    float* out = (float*)d_out;

    edt_rows<<<H, W>>>(in);
    edt_cols<<<H, W>>>(out);
}

// round 3
// speedup vs baseline: 1.3897x; 1.2316x over previous
#include <cuda_runtime.h>
#include <math.h>

#define H 128
#define W 128
#define B 8
#define SENT (1 << 28)
#define NBLK 128
#define NTHR 512

// Cross-block scratch + barrier counter (no device allocation allowed).
__device__ int g_G[H * W];
__device__ unsigned g_bar = 0;

__global__ void __launch_bounds__(NTHR, 1)
edt_fused(const float* __restrict__ in, float* __restrict__ out) {
    const int tid = threadIdx.x;
    const int j   = tid & 127;   // column
    const int p   = tid >> 7;    // quarter 0..3
    const int row = blockIdx.x;  // phase 1: h ; phase 2: i

    __shared__ unsigned s_mask[4];
    __shared__ int      s_part[4][W];
    __shared__ float    s_res[W];

    // ---------- Phase 1: build row mask (union over batch) ----------
    if (tid < 128) {
        bool m = false;
#pragma unroll
        for (int b = 0; b < B; b++)
            m |= in[b * (H * W) + row * W + j] > 0.5f;
        unsigned bal = __ballot_sync(0xFFFFFFFFu, m);
        if ((tid & 31) == 0) s_mask[tid >> 5] = bal;
    }
    __syncthreads();

    // 1D transform: thread (j,p) scans w in [32p, 32p+32) from one mask word.
    {
        const unsigned mw = s_mask[p];
        const int base = p << 5;
        int best = SENT;
#pragma unroll
        for (int k = 0; k < 32; k++) {
            int w = base + k;
            int d = j - w;
            int set = (int)((mw >> k) & 1u);       // 1 if boundary
            int v = (d * d) | ((set - 1) & SENT);  // +SENT bits when not set
            best = min(best, v);
        }
        s_part[p][j] = best;
    }
    __syncthreads();

    if (tid < 128) {
        int g = min(min(s_part[0][j], s_part[1][j]),
                    min(s_part[2][j], s_part[3][j]));
        __stcg(&g_G[row * W + j], g);  // L2, visible across SMs
    }

    // ---------- Software grid barrier (all 128 CTAs resident) ----------
    __threadfence();   // release g_G writes to GPU scope
    __syncthreads();
    if (tid == 0) {
        unsigned ticket = atomicAdd(&g_bar, 1u);
        unsigned target = (ticket / NBLK + 1u) * NBLK;  // generation-safe across replays
        volatile unsigned* vb = &g_bar;
        while (*vb < target) { }
        __threadfence();  // acquire before consuming g_G
    }
    __syncthreads();

    // ---------- Phase 2: thread (j,p) scans h in [32p, 32p+32) ----------
    {
        const int hbase = p << 5;
        const int* gcol = g_G + j;
        int best = SENT;
#pragma unroll
        for (int k = 0; k < 32; k++) {
            int h = hbase + k;
            int d = row - h;
            best = min(best, d * d + __ldcg(gcol + h * W));  // coalesced, MLP=32
        }
        s_part[p][j] = best;
    }
    __syncthreads();

    if (tid < 128) {
        int b4 = min(min(s_part[0][j], s_part[1][j]),
                     min(s_part[2][j], s_part[3][j]));
        s_res[j] = (b4 >= SENT) ? INFINITY : sqrtf((float)b4);
    }
    __syncthreads();

    // Broadcast write: quarter p writes batches 2p and 2p+1.
    {
        float r = s_res[j];
        out[(2 * p)     * (H * W) + row * W + j] = r;
        out[(2 * p + 1) * (H * W) + row * W + j] = r;
    }
}

extern "C" void kernel_launch(void* const* d_in, const int* in_sizes, int n_in,
                              void* d_out, int out_size) {
    const float* in = (const float*)d_in[0];
    float* out = (float*)d_out;
    edt_fused<<<NBLK, NTHR>>>(in, out);
}